// round 10
// baseline (speedup 1.0000x reference)
#include <cuda_runtime.h>
#include <cuda_bf16.h>
#include <mma.h>
#include <math.h>

using namespace nvcuda;

// ---------------- compile-time constants ----------------
constexpr int HH = 1024;
constexpr int II = 256;
constexpr int BB = 64;
constexpr int TT = 512;
constexpr int G4 = 4096;                 // 4*H
constexpr int MM = BB * TT;              // 32768

constexpr int NCTA   = 128;              // persistent grid: 1 CTA/SM
constexpr int APITCH = 72;               // A smem row pitch (bf16 elems)
constexpr int BPITCH = 1032;             // B smem row pitch (bf16 elems)
constexpr int KCH    = 64;               // K chunk staged per iteration

// smem byte offsets for the persistent kernel
constexpr unsigned SMB_BSH = 0;
constexpr unsigned SMB_BSL = SMB_BSH + 32u * BPITCH * 2u;
constexpr unsigned SMB_ASH = SMB_BSL + 32u * BPITCH * 2u;
constexpr unsigned SMB_ASL = SMB_ASH + 2u * 64u * APITCH * 2u;
constexpr unsigned SMB_GS  = SMB_ASL + 2u * 64u * APITCH * 2u;
constexpr unsigned SMB_CS  = SMB_GS + 64u * 40u * 4u;
constexpr unsigned SMB_BH  = SMB_CS + 64u * 8u * 4u;
constexpr unsigned SMB_TOT = SMB_BH + 32u * 4u;                   // 181376

// ---------------- scratch (static device globals; no allocation) ----------------
__device__ float         g_xg [(size_t)MM * G4];       // [B*T, 4H] x@W_ih^T + b_ih
__device__ __nv_bfloat16 g_hhi[(size_t)TT * BB * HH];  // h history, bf16 hi
__device__ __nv_bfloat16 g_hlo[(size_t)TT * BB * HH];  // h history, bf16 lo
__device__ __nv_bfloat16 g_xhi[(size_t)MM * II];       // x split hi
__device__ __nv_bfloat16 g_xlo[(size_t)MM * II];       // x split lo
__device__ __nv_bfloat16 g_whi[(size_t)G4 * II];       // W_ih split hi
__device__ __nv_bfloat16 g_wlo[(size_t)G4 * II];       // W_ih split lo

// ---------------- device-wide barrier (self-resetting across graph replays) -----
__device__ unsigned          g_bar_count = 0;
__device__ volatile unsigned g_bar_gen   = 0;

// =====================================================================
// split fp32 -> bf16 hi/lo
// =====================================================================
__global__ __launch_bounds__(256) void cvt_split(const float* __restrict__ src,
                                                 __nv_bfloat16* __restrict__ dhi,
                                                 __nv_bfloat16* __restrict__ dlo,
                                                 int n)
{
    const int i = blockIdx.x * 256 + threadIdx.x;
    if (i < n) {
        const float v = src[i];
        const __nv_bfloat16 hi = __float2bfloat16(v);
        dhi[i] = hi;
        dlo[i] = __float2bfloat16(v - __bfloat162float(hi));
    }
}

// =====================================================================
// xg GEMM via split-bf16 WMMA: xg[m][n] = sum_k x[m][k]*Wih[n][k] + bih[n]
// M=32768, N=4096, K=256. BM=64, BN=64, 256 thr.
// 8 warps: warp (wm, wn2) owns rows wm*16..+15, cols wn2*32..+31 (two 16x16 tiles).
// 3 accumulators per tile (HH gets bias preloaded; HL, LH zero), summed at end.
// =====================================================================
constexpr int XAP = 24;   // smem pitch (bf16 elems) for staged A/B tiles

__global__ __launch_bounds__(256) void xg_wmma(const float* __restrict__ bih)
{
    __shared__ __nv_bfloat16 AsH[2][64 * XAP];
    __shared__ __nv_bfloat16 AsL[2][64 * XAP];
    __shared__ __nv_bfloat16 BsH[2][64 * XAP];
    __shared__ __nv_bfloat16 BsL[2][64 * XAP];
    __shared__ float Bias2D[16 * 72];

    const int tid = threadIdx.x;
    const int n0  = blockIdx.x * 64;
    const int m0  = blockIdx.y * 64;

    // bias broadcast tile: rows 0..15 identical
    for (int i = tid; i < 16 * 64; i += 256)
        Bias2D[(i >> 6) * 72 + (i & 63)] = bih[n0 + (i & 63)];

    // staging roles: tid<128 -> A, else B. Each handles one uint4 (8 bf16) per part.
    const int half = tid >> 7;
    const int li   = tid & 127;
    const int srow = li >> 1;
    const int sk8  = (li & 1) * 8;

    const __nv_bfloat16* srcH = half ? (g_whi + (size_t)(n0 + srow) * II + sk8)
                                     : (g_xhi + (size_t)(m0 + srow) * II + sk8);
    const __nv_bfloat16* srcL = half ? (g_wlo + (size_t)(n0 + srow) * II + sk8)
                                     : (g_xlo + (size_t)(m0 + srow) * II + sk8);
    __nv_bfloat16* dstH0 = half ? &BsH[0][srow * XAP + sk8] : &AsH[0][srow * XAP + sk8];
    __nv_bfloat16* dstL0 = half ? &BsL[0][srow * XAP + sk8] : &AsL[0][srow * XAP + sk8];
    __nv_bfloat16* dstH1 = half ? &BsH[1][srow * XAP + sk8] : &AsH[1][srow * XAP + sk8];
    __nv_bfloat16* dstL1 = half ? &BsL[1][srow * XAP + sk8] : &AsL[1][srow * XAP + sk8];

    // prologue: stage kt=0
    uint4 rH = *(const uint4*)(srcH);
    uint4 rL = *(const uint4*)(srcL);
    *(uint4*)dstH0 = rH;
    *(uint4*)dstL0 = rL;
    __syncthreads();

    const int warp = tid >> 5;
    const int wm   = warp & 3;           // M tile row
    const int wn2  = warp >> 2;          // N 32-col group

    wmma::fragment<wmma::accumulator, 16, 16, 16, float> fS[2], fHL[2], fLH[2];
#pragma unroll
    for (int t = 0; t < 2; t++) {
        wmma::load_matrix_sync(fS[t], Bias2D + wn2 * 32 + t * 16, 72, wmma::mem_row_major);
        wmma::fill_fragment(fHL[t], 0.0f);
        wmma::fill_fragment(fLH[t], 0.0f);
    }

    for (int kt = 0; kt < 16; kt++) {
        const int buf = kt & 1;
        if (kt < 15) {
            rH = *(const uint4*)(srcH + (kt + 1) * 16);
            rL = *(const uint4*)(srcL + (kt + 1) * 16);
        }

        wmma::fragment<wmma::matrix_a, 16, 16, 16, __nv_bfloat16, wmma::row_major> faH, faL;
        wmma::load_matrix_sync(faH, &AsH[buf][wm * 16 * XAP], XAP);
        wmma::load_matrix_sync(faL, &AsL[buf][wm * 16 * XAP], XAP);
#pragma unroll
        for (int t = 0; t < 2; t++) {
            wmma::fragment<wmma::matrix_b, 16, 16, 16, __nv_bfloat16, wmma::col_major> fbH, fbL;
            wmma::load_matrix_sync(fbH, &BsH[buf][(wn2 * 32 + t * 16) * XAP], XAP);
            wmma::load_matrix_sync(fbL, &BsL[buf][(wn2 * 32 + t * 16) * XAP], XAP);
            wmma::mma_sync(fS[t],  faH, fbH, fS[t]);
            wmma::mma_sync(fHL[t], faH, fbL, fHL[t]);
            wmma::mma_sync(fLH[t], faL, fbH, fLH[t]);
        }

        if (kt < 15) {
            if (buf == 0) { *(uint4*)dstH1 = rH; *(uint4*)dstL1 = rL; }
            else          { *(uint4*)dstH0 = rH; *(uint4*)dstL0 = rL; }
        }
        __syncthreads();
    }

#pragma unroll
    for (int t = 0; t < 2; t++) {
#pragma unroll
        for (int e = 0; e < fS[t].num_elements; e++)
            fS[t].x[e] += fHL[t].x[e] + fLH[t].x[e];
        wmma::store_matrix_sync(g_xg + (size_t)(m0 + wm * 16) * G4 + n0 + wn2 * 32 + t * 16,
                                fS[t], G4, wmma::mem_row_major);
    }
}

// =====================================================================
// device-wide barrier
// =====================================================================
__device__ __forceinline__ void grid_sync_()
{
    __threadfence();
    __syncthreads();
    if (threadIdx.x == 0) {
        const unsigned gen = g_bar_gen;
        if (atomicAdd(&g_bar_count, 1u) == (unsigned)gridDim.x - 1u) {
            g_bar_count = 0;
            __threadfence();
            g_bar_gen = gen + 1u;
        } else {
            while (g_bar_gen == gen) { __nanosleep(64); }
        }
        __threadfence();
    }
    __syncthreads();
}

// =====================================================================
// Persistent LSTM recurrence: split-bf16 WMMA with 3 independent
// accumulator chains (HH / HL / LH) to break the HMMA RAW chain.
// =====================================================================
__global__ __launch_bounds__(256) void lstm_persistent(const float* __restrict__ Whh,
                                                       const float* __restrict__ bhh)
{
    extern __shared__ char smraw[];
    __nv_bfloat16* BsH = (__nv_bfloat16*)(smraw + SMB_BSH);
    __nv_bfloat16* BsL = (__nv_bfloat16*)(smraw + SMB_BSL);
    __nv_bfloat16* AsH = (__nv_bfloat16*)(smraw + SMB_ASH);
    __nv_bfloat16* AsL = (__nv_bfloat16*)(smraw + SMB_ASL);
    float* Gs = (float*)(smraw + SMB_GS);
    float* Cs = (float*)(smraw + SMB_CS);
    float* Bh = (float*)(smraw + SMB_BH);

    const int tid  = threadIdx.x;
    const int warp = tid >> 5;
    const int u0   = blockIdx.x * 8;

    // ---- one-time: split W_hh slice into smem hi/lo bf16 ----
    {
        const int c  = tid >> 3;
        const int e8 = tid & 7;
        const int grow = (c >> 3) * HH + u0 + (c & 7);
        const float* wr = Whh + (size_t)grow * HH;
        for (int q = 0; q < 32; q++) {
            const int k = e8 * 128 + q * 4;
            const float4 v = *(const float4*)(wr + k);
            const __nv_bfloat16 b0 = __float2bfloat16(v.x);
            const __nv_bfloat16 b1 = __float2bfloat16(v.y);
            const __nv_bfloat16 b2 = __float2bfloat16(v.z);
            const __nv_bfloat16 b3 = __float2bfloat16(v.w);
            BsH[c * BPITCH + k + 0] = b0;
            BsH[c * BPITCH + k + 1] = b1;
            BsH[c * BPITCH + k + 2] = b2;
            BsH[c * BPITCH + k + 3] = b3;
            BsL[c * BPITCH + k + 0] = __float2bfloat16(v.x - __bfloat162float(b0));
            BsL[c * BPITCH + k + 1] = __float2bfloat16(v.y - __bfloat162float(b1));
            BsL[c * BPITCH + k + 2] = __float2bfloat16(v.z - __bfloat162float(b2));
            BsL[c * BPITCH + k + 3] = __float2bfloat16(v.w - __bfloat162float(b3));
        }
    }
    if (tid < 32) Bh[tid] = bhh[(tid >> 3) * HH + u0 + (tid & 7)];
    for (int i = tid; i < 64 * 8; i += 256) Cs[i] = 0.f;
    __syncthreads();

    const int wm = warp & 3;
    const int wn = warp >> 2;

    const int cp_row = tid >> 2;
    const int cp_q   = tid & 3;

    const int pb = tid >> 2;
    const int pu = (tid & 3) * 2;

    for (int t = 0; t < TT; t++) {
        wmma::fragment<wmma::accumulator, 16, 16, 16, float> fS, fHL, fLH;
        wmma::fill_fragment(fS, 0.0f);
        wmma::fill_fragment(fHL, 0.0f);
        wmma::fill_fragment(fLH, 0.0f);

        if (t > 0) {
            const __nv_bfloat16* hHp = g_hhi + (size_t)(t - 1) * BB * HH;
            const __nv_bfloat16* hLp = g_hlo + (size_t)(t - 1) * BB * HH;
            const size_t rbase = (size_t)cp_row * HH + cp_q * 16;

            uint4 rh0 = *(const uint4*)(hHp + rbase);
            uint4 rh1 = *(const uint4*)(hHp + rbase + 8);
            uint4 rl0 = *(const uint4*)(hLp + rbase);
            uint4 rl1 = *(const uint4*)(hLp + rbase + 8);
            {
                const int so = cp_row * APITCH + cp_q * 16;
                *(uint4*)(AsH + so)     = rh0;
                *(uint4*)(AsH + so + 8) = rh1;
                *(uint4*)(AsL + so)     = rl0;
                *(uint4*)(AsL + so + 8) = rl1;
            }
            __syncthreads();

            for (int kt = 0; kt < 16; kt++) {
                const int buf = kt & 1;
                if (kt < 15) {
                    const size_t ro = rbase + (size_t)(kt + 1) * KCH;
                    rh0 = *(const uint4*)(hHp + ro);
                    rh1 = *(const uint4*)(hHp + ro + 8);
                    rl0 = *(const uint4*)(hLp + ro);
                    rl1 = *(const uint4*)(hLp + ro + 8);
                }

                const __nv_bfloat16* aH = AsH + buf * 64 * APITCH + wm * 16 * APITCH;
                const __nv_bfloat16* aL = AsL + buf * 64 * APITCH + wm * 16 * APITCH;
                const __nv_bfloat16* bH = BsH + wn * 16 * BPITCH + kt * KCH;
                const __nv_bfloat16* bL = BsL + wn * 16 * BPITCH + kt * KCH;

#pragma unroll
                for (int ks = 0; ks < 4; ks++) {
                    wmma::fragment<wmma::matrix_a, 16, 16, 16, __nv_bfloat16, wmma::row_major> faH, faL;
                    wmma::fragment<wmma::matrix_b, 16, 16, 16, __nv_bfloat16, wmma::col_major> fbH, fbL;
                    wmma::load_matrix_sync(faH, aH + ks * 16, APITCH);
                    wmma::load_matrix_sync(faL, aL + ks * 16, APITCH);
                    wmma::load_matrix_sync(fbH, bH + ks * 16, BPITCH);
                    wmma::load_matrix_sync(fbL, bL + ks * 16, BPITCH);
                    wmma::mma_sync(fS,  faH, fbH, fS);   // chain 1
                    wmma::mma_sync(fHL, faH, fbL, fHL);  // chain 2
                    wmma::mma_sync(fLH, faL, fbH, fLH);  // chain 3
                }

                if (kt < 15) {
                    const int so = (buf ^ 1) * 64 * APITCH + cp_row * APITCH + cp_q * 16;
                    *(uint4*)(AsH + so)     = rh0;
                    *(uint4*)(AsH + so + 8) = rh1;
                    *(uint4*)(AsL + so)     = rl0;
                    *(uint4*)(AsL + so + 8) = rl1;
                }
                __syncthreads();
            }
        }

        // ---- sum chains, stash D tile to Gs ----
#pragma unroll
        for (int e = 0; e < fS.num_elements; e++)
            fS.x[e] += fHL.x[e] + fLH.x[e];
        wmma::store_matrix_sync(Gs + wm * 16 * 40 + wn * 16, fS, 40, wmma::mem_row_major);
        __syncthreads();

        // ---- pointwise: gates -> c,h; write h as bf16 hi/lo ----
        {
            const size_t xbase = ((size_t)pb * TT + t) * G4 + u0 + pu;
            const float2 vxi = *(const float2*)(g_xg + xbase);
            const float2 vxf = *(const float2*)(g_xg + xbase + HH);
            const float2 vxg = *(const float2*)(g_xg + xbase + 2 * HH);
            const float2 vxo = *(const float2*)(g_xg + xbase + 3 * HH);

            const float2 vri = *(const float2*)(Gs + pb * 40 + 0  + pu);
            const float2 vrf = *(const float2*)(Gs + pb * 40 + 8  + pu);
            const float2 vrg = *(const float2*)(Gs + pb * 40 + 16 + pu);
            const float2 vro = *(const float2*)(Gs + pb * 40 + 24 + pu);

            const float2 vcp = *(const float2*)(Cs + pb * 8 + pu);

            const float i0 = 1.f / (1.f + expf(-(vxi.x + vri.x + Bh[pu])));
            const float f0 = 1.f / (1.f + expf(-(vxf.x + vrf.x + Bh[8 + pu])));
            const float g0 = tanhf(vxg.x + vrg.x + Bh[16 + pu]);
            const float o0 = 1.f / (1.f + expf(-(vxo.x + vro.x + Bh[24 + pu])));
            const float c0 = f0 * vcp.x + i0 * g0;
            const float h0 = o0 * tanhf(c0);

            const float i1 = 1.f / (1.f + expf(-(vxi.y + vri.y + Bh[pu + 1])));
            const float f1 = 1.f / (1.f + expf(-(vxf.y + vrf.y + Bh[9 + pu])));
            const float g1 = tanhf(vxg.y + vrg.y + Bh[17 + pu]);
            const float o1 = 1.f / (1.f + expf(-(vxo.y + vro.y + Bh[25 + pu])));
            const float c1 = f1 * vcp.y + i1 * g1;
            const float h1 = o1 * tanhf(c1);

            *(float2*)(Cs + pb * 8 + pu) = make_float2(c0, c1);

            const __nv_bfloat16 h0h = __float2bfloat16(h0);
            const __nv_bfloat16 h1h = __float2bfloat16(h1);
            const __nv_bfloat16 h0l = __float2bfloat16(h0 - __bfloat162float(h0h));
            const __nv_bfloat16 h1l = __float2bfloat16(h1 - __bfloat162float(h1h));

            const size_t hidx = ((size_t)t * BB + pb) * HH + u0 + pu;
            g_hhi[hidx]     = h0h;
            g_hhi[hidx + 1] = h1h;
            g_hlo[hidx]     = h0l;
            g_hlo[hidx + 1] = h1l;
        }

        grid_sync_();
    }
}

// =====================================================================
// FC: out[b][t] = dot(h_t[b], W_fc) + b_fc   (h = hi + lo)
// =====================================================================
__global__ __launch_bounds__(128) void fc_kernel(const float* __restrict__ Wfc,
                                                 const float* __restrict__ bfc,
                                                 float* __restrict__ out)
{
    const int bt = blockIdx.x;
    const int t  = bt >> 6;
    const int b  = bt & 63;
    const size_t base = ((size_t)t * BB + b) * HH;
    const int tid = threadIdx.x;

    float s = 0.f;
#pragma unroll
    for (int q = 0; q < 8; q++) {
        const int j = tid + q * 128;
        const float h = __bfloat162float(g_hhi[base + j]) + __bfloat162float(g_hlo[base + j]);
        s += h * Wfc[j];
    }
#pragma unroll
    for (int off = 16; off; off >>= 1) s += __shfl_down_sync(0xffffffffu, s, off);

    __shared__ float red[4];
    if ((tid & 31) == 0) red[tid >> 5] = s;
    __syncthreads();
    if (tid == 0)
        out[(size_t)b * TT + t] = red[0] + red[1] + red[2] + red[3] + bfc[0];
}

// =====================================================================
extern "C" void kernel_launch(void* const* d_in, const int* in_sizes, int n_in,
                              void* d_out, int out_size)
{
    const float* x   = (const float*)d_in[0];
    const float* Wih = (const float*)d_in[1];
    const float* Whh = (const float*)d_in[2];
    const float* bih = (const float*)d_in[3];
    const float* bhh = (const float*)d_in[4];
    const float* Wfc = (const float*)d_in[5];
    const float* bfc = (const float*)d_in[6];
    float* out = (float*)d_out;

    cudaFuncSetAttribute(lstm_persistent,
                         cudaFuncAttributeMaxDynamicSharedMemorySize, (int)SMB_TOT);

    // 1) split x and W_ih into bf16 hi/lo
    {
        __nv_bfloat16 *xhi = nullptr, *xlo = nullptr, *whi = nullptr, *wlo = nullptr;
        cudaGetSymbolAddress((void**)&xhi, g_xhi);
        cudaGetSymbolAddress((void**)&xlo, g_xlo);
        cudaGetSymbolAddress((void**)&whi, g_whi);
        cudaGetSymbolAddress((void**)&wlo, g_wlo);
        cvt_split<<<(MM * II + 255) / 256, 256>>>(x, xhi, xlo, MM * II);
        cvt_split<<<(G4 * II + 255) / 256, 256>>>(Wih, whi, wlo, G4 * II);
    }

    // 2) input projection: split-bf16 tensor-core GEMM
    xg_wmma<<<dim3(G4 / 64, MM / 64), 256>>>(bih);

    // 3) full recurrence: one persistent tensor-core kernel
    lstm_persistent<<<NCTA, 256, SMB_TOT>>>(Whh, bhh);

    // 4) output projection
    fc_kernel<<<MM, 128>>>(Wfc, bfc, out);
}

// round 14
// speedup vs baseline: 1.4374x; 1.4374x over previous
#include <cuda_runtime.h>
#include <cuda_bf16.h>
#include <mma.h>
#include <math.h>

using namespace nvcuda;

// ---------------- compile-time constants (no object-like macros) ----------------
constexpr int HH = 1024;
constexpr int II = 256;
constexpr int BB = 64;
constexpr int TT = 512;
constexpr int G4 = 4096;                 // 4*H
constexpr int MM = BB * TT;              // 32768

constexpr int NCTA   = 128;              // persistent grid: 1 CTA/SM, co-resident
constexpr int APITCH = 72;               // A smem row pitch (bf16 elems), 144 B
constexpr int BPITCH = 1032;             // B smem row pitch (bf16 elems), 2064 B
constexpr int KCH    = 64;               // K chunk staged per iteration

// smem byte offsets for the persistent kernel
constexpr unsigned SMB_BSH = 0;                                   // 32*BPITCH bf16
constexpr unsigned SMB_BSL = SMB_BSH + 32u * BPITCH * 2u;         // 66048
constexpr unsigned SMB_ASH = SMB_BSL + 32u * BPITCH * 2u;         // 132096
constexpr unsigned SMB_ASL = SMB_ASH + 2u * 64u * APITCH * 2u;    // 150528
constexpr unsigned SMB_GS  = SMB_ASL + 2u * 64u * APITCH * 2u;    // 168960
constexpr unsigned SMB_CS  = SMB_GS + 64u * 40u * 4u;             // 179200
constexpr unsigned SMB_BH  = SMB_CS + 64u * 8u * 4u;              // 181248
constexpr unsigned SMB_TOT = SMB_BH + 32u * 4u;                   // 181376

// ---------------- scratch (static device globals; no allocation) ----------------
__device__ float         g_xg [(size_t)MM * G4];       // [B*T, 4H] x@W_ih^T + b_ih
__device__ __nv_bfloat16 g_hhi[(size_t)TT * BB * HH];  // h history, bf16 high part
__device__ __nv_bfloat16 g_hlo[(size_t)TT * BB * HH];  // h history, bf16 low part

// ---------------- device-wide barrier (self-resetting across graph replays) -----
__device__ unsigned          g_bar_count = 0;
__device__ volatile unsigned g_bar_gen   = 0;

// =====================================================================
// Kernel 1: xg[m][n] = sum_k x[m][k]*W_ih[n][k] + b_ih[n]   (fp32 SIMT)
// (round-9 known-good version, restored verbatim)
// =====================================================================
__global__ __launch_bounds__(256) void xg_gemm(const float* __restrict__ x,
                                               const float* __restrict__ Wih,
                                               const float* __restrict__ bih)
{
    const int BM = 128, BN = 64, BKi = 16;
    __shared__ float As[2][16][BM + 4];
    __shared__ float Ws[2][16][BN + 4];

    const int n0  = blockIdx.x * BN;
    const int m0  = blockIdx.y * BM;
    const int tid = threadIdx.x;
    const int tr  = tid / 16;
    const int tc  = tid % 16;

    const int a_row0 = (tid)       >> 2, a_kq0 = (tid)       & 3;
    const int a_row1 = (tid + 256) >> 2, a_kq1 = (tid + 256) & 3;
    const int w_row  = tid >> 2,         w_kq  = tid & 3;

    float acc[8][4];
#pragma unroll
    for (int i = 0; i < 8; i++)
#pragma unroll
        for (int j = 0; j < 4; j++) acc[i][j] = 0.f;

    float4 a0, a1, wv;

    // prologue: tile 0
    a0 = *(const float4*)&x[(size_t)(m0 + a_row0) * II + a_kq0 * 4];
    a1 = *(const float4*)&x[(size_t)(m0 + a_row1) * II + a_kq1 * 4];
    wv = *(const float4*)&Wih[(size_t)(n0 + w_row) * II + w_kq * 4];
    As[0][a_kq0*4+0][a_row0] = a0.x; As[0][a_kq0*4+1][a_row0] = a0.y;
    As[0][a_kq0*4+2][a_row0] = a0.z; As[0][a_kq0*4+3][a_row0] = a0.w;
    As[0][a_kq1*4+0][a_row1] = a1.x; As[0][a_kq1*4+1][a_row1] = a1.y;
    As[0][a_kq1*4+2][a_row1] = a1.z; As[0][a_kq1*4+3][a_row1] = a1.w;
    Ws[0][w_kq*4+0][w_row]   = wv.x; Ws[0][w_kq*4+1][w_row]   = wv.y;
    Ws[0][w_kq*4+2][w_row]   = wv.z; Ws[0][w_kq*4+3][w_row]   = wv.w;
    __syncthreads();

    const int NIT = II / BKi; // 16
    for (int it = 0; it < NIT; it++) {
        const int cur = it & 1;
        if (it + 1 < NIT) {
            const int k0 = (it + 1) * BKi;
            a0 = *(const float4*)&x[(size_t)(m0 + a_row0) * II + k0 + a_kq0 * 4];
            a1 = *(const float4*)&x[(size_t)(m0 + a_row1) * II + k0 + a_kq1 * 4];
            wv = *(const float4*)&Wih[(size_t)(n0 + w_row) * II + k0 + w_kq * 4];
        }
#pragma unroll
        for (int kk = 0; kk < 16; kk++) {
            float a[8], w[4];
#pragma unroll
            for (int i = 0; i < 8; i++) a[i] = As[cur][kk][tr * 8 + i];
#pragma unroll
            for (int j = 0; j < 4; j++) w[j] = Ws[cur][kk][tc * 4 + j];
#pragma unroll
            for (int i = 0; i < 8; i++)
#pragma unroll
                for (int j = 0; j < 4; j++) acc[i][j] += a[i] * w[j];
        }
        if (it + 1 < NIT) {
            const int nxt = cur ^ 1;
            As[nxt][a_kq0*4+0][a_row0] = a0.x; As[nxt][a_kq0*4+1][a_row0] = a0.y;
            As[nxt][a_kq0*4+2][a_row0] = a0.z; As[nxt][a_kq0*4+3][a_row0] = a0.w;
            As[nxt][a_kq1*4+0][a_row1] = a1.x; As[nxt][a_kq1*4+1][a_row1] = a1.y;
            As[nxt][a_kq1*4+2][a_row1] = a1.z; As[nxt][a_kq1*4+3][a_row1] = a1.w;
            Ws[nxt][w_kq*4+0][w_row]   = wv.x; Ws[nxt][w_kq*4+1][w_row]   = wv.y;
            Ws[nxt][w_kq*4+2][w_row]   = wv.z; Ws[nxt][w_kq*4+3][w_row]   = wv.w;
        }
        __syncthreads();
    }

    const float4 bv = *(const float4*)&bih[n0 + tc * 4];
#pragma unroll
    for (int i = 0; i < 8; i++) {
        const size_t row = (size_t)(m0 + tr * 8 + i);
        float4 o;
        o.x = acc[i][0] + bv.x; o.y = acc[i][1] + bv.y;
        o.z = acc[i][2] + bv.z; o.w = acc[i][3] + bv.w;
        *(float4*)&g_xg[row * G4 + (n0 + tc * 4)] = o;
    }
}

// =====================================================================
// device-wide barrier
// =====================================================================
__device__ __forceinline__ void grid_sync_()
{
    __threadfence();
    __syncthreads();
    if (threadIdx.x == 0) {
        const unsigned gen = g_bar_gen;
        if (atomicAdd(&g_bar_count, 1u) == (unsigned)gridDim.x - 1u) {
            g_bar_count = 0;
            __threadfence();
            g_bar_gen = gen + 1u;
        } else {
            while (g_bar_gen == gen) { __nanosleep(64); }
        }
        __threadfence();
    }
    __syncthreads();
}

// =====================================================================
// Persistent LSTM recurrence: split-bf16 WMMA.
// ONLY change vs the 11,318us round-9 baseline: 3 independent
// accumulator chains (HH / HL / LH) instead of one, summed at the end,
// to break the HMMA RAW dependency chain (24 -> 8 dependent MMAs).
// =====================================================================
__global__ __launch_bounds__(256) void lstm_persistent(const float* __restrict__ Whh,
                                                       const float* __restrict__ bhh)
{
    extern __shared__ char smraw[];
    __nv_bfloat16* BsH = (__nv_bfloat16*)(smraw + SMB_BSH);
    __nv_bfloat16* BsL = (__nv_bfloat16*)(smraw + SMB_BSL);
    __nv_bfloat16* AsH = (__nv_bfloat16*)(smraw + SMB_ASH);
    __nv_bfloat16* AsL = (__nv_bfloat16*)(smraw + SMB_ASL);
    float* Gs = (float*)(smraw + SMB_GS);
    float* Cs = (float*)(smraw + SMB_CS);
    float* Bh = (float*)(smraw + SMB_BH);

    const int tid  = threadIdx.x;
    const int warp = tid >> 5;
    const int u0   = blockIdx.x * 8;       // first hidden unit owned by this CTA

    // ---- one-time: split W_hh slice into smem hi/lo bf16 ----
    {
        const int c  = tid >> 3;
        const int e8 = tid & 7;
        const int grow = (c >> 3) * HH + u0 + (c & 7);
        const float* wr = Whh + (size_t)grow * HH;
        for (int q = 0; q < 32; q++) {
            const int k = e8 * 128 + q * 4;
            const float4 v = *(const float4*)(wr + k);
            const __nv_bfloat16 b0 = __float2bfloat16(v.x);
            const __nv_bfloat16 b1 = __float2bfloat16(v.y);
            const __nv_bfloat16 b2 = __float2bfloat16(v.z);
            const __nv_bfloat16 b3 = __float2bfloat16(v.w);
            BsH[c * BPITCH + k + 0] = b0;
            BsH[c * BPITCH + k + 1] = b1;
            BsH[c * BPITCH + k + 2] = b2;
            BsH[c * BPITCH + k + 3] = b3;
            BsL[c * BPITCH + k + 0] = __float2bfloat16(v.x - __bfloat162float(b0));
            BsL[c * BPITCH + k + 1] = __float2bfloat16(v.y - __bfloat162float(b1));
            BsL[c * BPITCH + k + 2] = __float2bfloat16(v.z - __bfloat162float(b2));
            BsL[c * BPITCH + k + 3] = __float2bfloat16(v.w - __bfloat162float(b3));
        }
    }
    if (tid < 32) Bh[tid] = bhh[(tid >> 3) * HH + u0 + (tid & 7)];
    for (int i = tid; i < 64 * 8; i += 256) Cs[i] = 0.f;
    __syncthreads();

    const int wm = warp & 3;               // M tile base (batch rows)
    const int wn = warp >> 2;              // N tile base (local cols)

    const int cp_row = tid >> 2;           // 0..63
    const int cp_q   = tid & 3;            // 0..3

    const int pb = tid >> 2;               // batch 0..63
    const int pu = (tid & 3) * 2;          // unit pair 0,2,4,6

    for (int t = 0; t < TT; t++) {
        wmma::fragment<wmma::accumulator, 16, 16, 16, float> fS, fHL, fLH;
        wmma::fill_fragment(fS, 0.0f);
        wmma::fill_fragment(fHL, 0.0f);
        wmma::fill_fragment(fLH, 0.0f);

        if (t > 0) {
            const __nv_bfloat16* hHp = g_hhi + (size_t)(t - 1) * BB * HH;
            const __nv_bfloat16* hLp = g_hlo + (size_t)(t - 1) * BB * HH;
            const size_t rbase = (size_t)cp_row * HH + cp_q * 16;

            uint4 rh0 = *(const uint4*)(hHp + rbase);
            uint4 rh1 = *(const uint4*)(hHp + rbase + 8);
            uint4 rl0 = *(const uint4*)(hLp + rbase);
            uint4 rl1 = *(const uint4*)(hLp + rbase + 8);
            {
                const int so = cp_row * APITCH + cp_q * 16;
                *(uint4*)(AsH + so)     = rh0;
                *(uint4*)(AsH + so + 8) = rh1;
                *(uint4*)(AsL + so)     = rl0;
                *(uint4*)(AsL + so + 8) = rl1;
            }
            __syncthreads();

            for (int kt = 0; kt < 16; kt++) {          // 16 chunks of KCH=64
                const int buf = kt & 1;
                if (kt < 15) {
                    const size_t ro = rbase + (size_t)(kt + 1) * KCH;
                    rh0 = *(const uint4*)(hHp + ro);
                    rh1 = *(const uint4*)(hHp + ro + 8);
                    rl0 = *(const uint4*)(hLp + ro);
                    rl1 = *(const uint4*)(hLp + ro + 8);
                }

                const __nv_bfloat16* aH = AsH + buf * 64 * APITCH + wm * 16 * APITCH;
                const __nv_bfloat16* aL = AsL + buf * 64 * APITCH + wm * 16 * APITCH;
                const __nv_bfloat16* bH = BsH + wn * 16 * BPITCH + kt * KCH;
                const __nv_bfloat16* bL = BsL + wn * 16 * BPITCH + kt * KCH;

#pragma unroll
                for (int ks = 0; ks < 4; ks++) {       // 4 k-steps of 16 per chunk
                    wmma::fragment<wmma::matrix_a, 16, 16, 16, __nv_bfloat16, wmma::row_major> faH, faL;
                    wmma::fragment<wmma::matrix_b, 16, 16, 16, __nv_bfloat16, wmma::col_major> fbH, fbL;
                    wmma::load_matrix_sync(faH, aH + ks * 16, APITCH);
                    wmma::load_matrix_sync(faL, aL + ks * 16, APITCH);
                    wmma::load_matrix_sync(fbH, bH + ks * 16, BPITCH);
                    wmma::load_matrix_sync(fbL, bL + ks * 16, BPITCH);
                    wmma::mma_sync(fS,  faH, fbH, fS);   // chain 1
                    wmma::mma_sync(fHL, faH, fbL, fHL);  // chain 2
                    wmma::mma_sync(fLH, faL, fbH, fLH);  // chain 3
                }

                if (kt < 15) {
                    const int so = (buf ^ 1) * 64 * APITCH + cp_row * APITCH + cp_q * 16;
                    *(uint4*)(AsH + so)     = rh0;
                    *(uint4*)(AsH + so + 8) = rh1;
                    *(uint4*)(AsL + so)     = rl0;
                    *(uint4*)(AsL + so + 8) = rl1;
                }
                __syncthreads();
            }
        }

        // ---- sum chains, stash D tile to Gs [64 rows][pitch 40] ----
#pragma unroll
        for (int e = 0; e < fS.num_elements; e++)
            fS.x[e] += fHL.x[e] + fLH.x[e];
        wmma::store_matrix_sync(Gs + wm * 16 * 40 + wn * 16, fS, 40, wmma::mem_row_major);
        __syncthreads();

        // ---- pointwise: gates -> c,h; write h as bf16 hi/lo ----
        {
            const size_t xbase = ((size_t)pb * TT + t) * G4 + u0 + pu;
            const float2 vxi = *(const float2*)(g_xg + xbase);
            const float2 vxf = *(const float2*)(g_xg + xbase + HH);
            const float2 vxg = *(const float2*)(g_xg + xbase + 2 * HH);
            const float2 vxo = *(const float2*)(g_xg + xbase + 3 * HH);

            const float2 vri = *(const float2*)(Gs + pb * 40 + 0  + pu);
            const float2 vrf = *(const float2*)(Gs + pb * 40 + 8  + pu);
            const float2 vrg = *(const float2*)(Gs + pb * 40 + 16 + pu);
            const float2 vro = *(const float2*)(Gs + pb * 40 + 24 + pu);

            const float2 vcp = *(const float2*)(Cs + pb * 8 + pu);

            const float i0 = 1.f / (1.f + expf(-(vxi.x + vri.x + Bh[pu])));
            const float f0 = 1.f / (1.f + expf(-(vxf.x + vrf.x + Bh[8 + pu])));
            const float g0 = tanhf(vxg.x + vrg.x + Bh[16 + pu]);
            const float o0 = 1.f / (1.f + expf(-(vxo.x + vro.x + Bh[24 + pu])));
            const float c0 = f0 * vcp.x + i0 * g0;
            const float h0 = o0 * tanhf(c0);

            const float i1 = 1.f / (1.f + expf(-(vxi.y + vri.y + Bh[pu + 1])));
            const float f1 = 1.f / (1.f + expf(-(vxf.y + vrf.y + Bh[9 + pu])));
            const float g1 = tanhf(vxg.y + vrg.y + Bh[17 + pu]);
            const float o1 = 1.f / (1.f + expf(-(vxo.y + vro.y + Bh[25 + pu])));
            const float c1 = f1 * vcp.y + i1 * g1;
            const float h1 = o1 * tanhf(c1);

            *(float2*)(Cs + pb * 8 + pu) = make_float2(c0, c1);

            const __nv_bfloat16 h0h = __float2bfloat16(h0);
            const __nv_bfloat16 h1h = __float2bfloat16(h1);
            const __nv_bfloat16 h0l = __float2bfloat16(h0 - __bfloat162float(h0h));
            const __nv_bfloat16 h1l = __float2bfloat16(h1 - __bfloat162float(h1h));

            const size_t hidx = ((size_t)t * BB + pb) * HH + u0 + pu;
            g_hhi[hidx]     = h0h;
            g_hhi[hidx + 1] = h1h;
            g_hlo[hidx]     = h0l;
            g_hlo[hidx + 1] = h1l;
        }

        grid_sync_();
    }
}

// =====================================================================
// FC: out[b][t] = dot(h_t[b], W_fc) + b_fc   (h = hi + lo)
// =====================================================================
__global__ __launch_bounds__(128) void fc_kernel(const float* __restrict__ Wfc,
                                                 const float* __restrict__ bfc,
                                                 float* __restrict__ out)
{
    const int bt = blockIdx.x;
    const int t  = bt >> 6;
    const int b  = bt & 63;
    const size_t base = ((size_t)t * BB + b) * HH;
    const int tid = threadIdx.x;

    float s = 0.f;
#pragma unroll
    for (int q = 0; q < 8; q++) {
        const int j = tid + q * 128;
        const float h = __bfloat162float(g_hhi[base + j]) + __bfloat162float(g_hlo[base + j]);
        s += h * Wfc[j];
    }
#pragma unroll
    for (int off = 16; off; off >>= 1) s += __shfl_down_sync(0xffffffffu, s, off);

    __shared__ float red[4];
    if ((tid & 31) == 0) red[tid >> 5] = s;
    __syncthreads();
    if (tid == 0)
        out[(size_t)b * TT + t] = red[0] + red[1] + red[2] + red[3] + bfc[0];
}

// =====================================================================
extern "C" void kernel_launch(void* const* d_in, const int* in_sizes, int n_in,
                              void* d_out, int out_size)
{
    const float* x   = (const float*)d_in[0];
    const float* Wih = (const float*)d_in[1];
    const float* Whh = (const float*)d_in[2];
    const float* bih = (const float*)d_in[3];
    const float* bhh = (const float*)d_in[4];
    const float* Wfc = (const float*)d_in[5];
    const float* bfc = (const float*)d_in[6];
    float* out = (float*)d_out;

    cudaFuncSetAttribute(lstm_persistent,
                         cudaFuncAttributeMaxDynamicSharedMemorySize, (int)SMB_TOT);

    // 1) input projection (fp32 SIMT GEMM, known-good 3.0 ms)
    xg_gemm<<<dim3(G4 / 64, MM / 128), 256>>>(x, Wih, bih);

    // 2) full recurrence: one persistent tensor-core kernel (3-chain version)
    lstm_persistent<<<NCTA, 256, SMB_TOT>>>(Whh, bhh);

    // 3) output projection
    fc_kernel<<<MM, 128>>>(Wfc, bfc, out);
}

// round 16
// speedup vs baseline: 1.7343x; 1.2066x over previous
#include <cuda_runtime.h>
#include <cuda_bf16.h>
#include <mma.h>
#include <math.h>

using namespace nvcuda;

// ---------------- compile-time constants ----------------
constexpr int HH = 1024;
constexpr int II = 256;
constexpr int BB = 64;
constexpr int TT = 512;
constexpr int G4 = 4096;                 // 4*H
constexpr int MM = BB * TT;              // 32768

constexpr int NCTA   = 128;              // persistent grid: 1 CTA/SM, co-resident
constexpr int APITCH = 72;               // A smem row pitch (bf16 elems), 144 B
constexpr int BPITCH = 1032;             // B smem row pitch (bf16 elems), 2064 B
constexpr int KCH    = 64;               // K chunk staged per iteration

// smem byte offsets for the persistent kernel
constexpr unsigned SMB_BSH = 0;                                   // 32*BPITCH bf16
constexpr unsigned SMB_BSL = SMB_BSH + 32u * BPITCH * 2u;         // 66048
constexpr unsigned SMB_ASH = SMB_BSL + 32u * BPITCH * 2u;         // 132096
constexpr unsigned SMB_ASL = SMB_ASH + 2u * 64u * APITCH * 2u;    // 150528
constexpr unsigned SMB_GS  = SMB_ASL + 2u * 64u * APITCH * 2u;    // 168960
constexpr unsigned SMB_CS  = SMB_GS + 64u * 40u * 4u;             // 179200
constexpr unsigned SMB_BH  = SMB_CS + 64u * 8u * 4u;              // 181248
constexpr unsigned SMB_TOT = SMB_BH + 32u * 4u;                   // 181376

// ---------------- scratch (static device globals; no allocation) ----------------
__device__ float         g_xg [(size_t)MM * G4];       // [B*T, 4H] x@W_ih^T + b_ih
__device__ __nv_bfloat16 g_hhi[(size_t)TT * BB * HH];  // h history, bf16 high part
__device__ __nv_bfloat16 g_hlo[(size_t)TT * BB * HH];  // h history, bf16 low part

// ---------------- device-wide barrier (self-resetting across graph replays) -----
__device__ unsigned          g_bar_count = 0;
__device__ volatile unsigned g_bar_gen   = 0;

// =====================================================================
// Kernel 1: xg[m][n] = sum_k x[m][k]*W_ih[n][k] + b_ih[n]   (fp32 SIMT)
// (known-good, measured ~3.0 ms — unchanged)
// =====================================================================
__global__ __launch_bounds__(256) void xg_gemm(const float* __restrict__ x,
                                               const float* __restrict__ Wih,
                                               const float* __restrict__ bih)
{
    const int BM = 128, BN = 64, BKi = 16;
    __shared__ float As[2][16][BM + 4];
    __shared__ float Ws[2][16][BN + 4];

    const int n0  = blockIdx.x * BN;
    const int m0  = blockIdx.y * BM;
    const int tid = threadIdx.x;
    const int tr  = tid / 16;
    const int tc  = tid % 16;

    const int a_row0 = (tid)       >> 2, a_kq0 = (tid)       & 3;
    const int a_row1 = (tid + 256) >> 2, a_kq1 = (tid + 256) & 3;
    const int w_row  = tid >> 2,         w_kq  = tid & 3;

    float acc[8][4];
#pragma unroll
    for (int i = 0; i < 8; i++)
#pragma unroll
        for (int j = 0; j < 4; j++) acc[i][j] = 0.f;

    float4 a0, a1, wv;

    a0 = *(const float4*)&x[(size_t)(m0 + a_row0) * II + a_kq0 * 4];
    a1 = *(const float4*)&x[(size_t)(m0 + a_row1) * II + a_kq1 * 4];
    wv = *(const float4*)&Wih[(size_t)(n0 + w_row) * II + w_kq * 4];
    As[0][a_kq0*4+0][a_row0] = a0.x; As[0][a_kq0*4+1][a_row0] = a0.y;
    As[0][a_kq0*4+2][a_row0] = a0.z; As[0][a_kq0*4+3][a_row0] = a0.w;
    As[0][a_kq1*4+0][a_row1] = a1.x; As[0][a_kq1*4+1][a_row1] = a1.y;
    As[0][a_kq1*4+2][a_row1] = a1.z; As[0][a_kq1*4+3][a_row1] = a1.w;
    Ws[0][w_kq*4+0][w_row]   = wv.x; Ws[0][w_kq*4+1][w_row]   = wv.y;
    Ws[0][w_kq*4+2][w_row]   = wv.z; Ws[0][w_kq*4+3][w_row]   = wv.w;
    __syncthreads();

    const int NIT = II / BKi; // 16
    for (int it = 0; it < NIT; it++) {
        const int cur = it & 1;
        if (it + 1 < NIT) {
            const int k0 = (it + 1) * BKi;
            a0 = *(const float4*)&x[(size_t)(m0 + a_row0) * II + k0 + a_kq0 * 4];
            a1 = *(const float4*)&x[(size_t)(m0 + a_row1) * II + k0 + a_kq1 * 4];
            wv = *(const float4*)&Wih[(size_t)(n0 + w_row) * II + k0 + w_kq * 4];
        }
#pragma unroll
        for (int kk = 0; kk < 16; kk++) {
            float a[8], w[4];
#pragma unroll
            for (int i = 0; i < 8; i++) a[i] = As[cur][kk][tr * 8 + i];
#pragma unroll
            for (int j = 0; j < 4; j++) w[j] = Ws[cur][kk][tc * 4 + j];
#pragma unroll
            for (int i = 0; i < 8; i++)
#pragma unroll
                for (int j = 0; j < 4; j++) acc[i][j] += a[i] * w[j];
        }
        if (it + 1 < NIT) {
            const int nxt = cur ^ 1;
            As[nxt][a_kq0*4+0][a_row0] = a0.x; As[nxt][a_kq0*4+1][a_row0] = a0.y;
            As[nxt][a_kq0*4+2][a_row0] = a0.z; As[nxt][a_kq0*4+3][a_row0] = a0.w;
            As[nxt][a_kq1*4+0][a_row1] = a1.x; As[nxt][a_kq1*4+1][a_row1] = a1.y;
            As[nxt][a_kq1*4+2][a_row1] = a1.z; As[nxt][a_kq1*4+3][a_row1] = a1.w;
            Ws[nxt][w_kq*4+0][w_row]   = wv.x; Ws[nxt][w_kq*4+1][w_row]   = wv.y;
            Ws[nxt][w_kq*4+2][w_row]   = wv.z; Ws[nxt][w_kq*4+3][w_row]   = wv.w;
        }
        __syncthreads();
    }

    const float4 bv = *(const float4*)&bih[n0 + tc * 4];
#pragma unroll
    for (int i = 0; i < 8; i++) {
        const size_t row = (size_t)(m0 + tr * 8 + i);
        float4 o;
        o.x = acc[i][0] + bv.x; o.y = acc[i][1] + bv.y;
        o.z = acc[i][2] + bv.z; o.w = acc[i][3] + bv.w;
        *(float4*)&g_xg[row * G4 + (n0 + tc * 4)] = o;
    }
}

// =====================================================================
// device-wide barrier
// =====================================================================
__device__ __forceinline__ void grid_sync_()
{
    __threadfence();
    __syncthreads();
    if (threadIdx.x == 0) {
        const unsigned gen = g_bar_gen;
        if (atomicAdd(&g_bar_count, 1u) == (unsigned)gridDim.x - 1u) {
            g_bar_count = 0;
            __threadfence();
            g_bar_gen = gen + 1u;
        } else {
            while (g_bar_gen == gen) { __nanosleep(64); }
        }
        __threadfence();
    }
    __syncthreads();
}

// =====================================================================
// Persistent LSTM recurrence: split-bf16 WMMA, WARP-SPECIALIZED.
// 512 threads: warps 0-7 = MMA consumers (16x16 tile each, 3 chains),
//              warps 8-15 = producers staging A (h_prev hi/lo) chunks.
// Producers fill buf^1 while consumers compute on buf; per-kt
// __syncthreads is the hand-off. ONLY structural change vs the
// 11,228us round-14 baseline.
// =====================================================================
__global__ __launch_bounds__(512) void lstm_persistent(const float* __restrict__ Whh,
                                                       const float* __restrict__ bhh)
{
    extern __shared__ char smraw[];
    __nv_bfloat16* BsH = (__nv_bfloat16*)(smraw + SMB_BSH);
    __nv_bfloat16* BsL = (__nv_bfloat16*)(smraw + SMB_BSL);
    __nv_bfloat16* AsH = (__nv_bfloat16*)(smraw + SMB_ASH);
    __nv_bfloat16* AsL = (__nv_bfloat16*)(smraw + SMB_ASL);
    float* Gs = (float*)(smraw + SMB_GS);
    float* Cs = (float*)(smraw + SMB_CS);
    float* Bh = (float*)(smraw + SMB_BH);

    const int tid  = threadIdx.x;
    const int warp = tid >> 5;
    const int u0   = blockIdx.x * 8;       // first hidden unit owned by this CTA

    // ---- one-time: split W_hh slice into smem hi/lo bf16 (first 256 threads) ----
    if (tid < 256) {
        const int c  = tid >> 3;
        const int e8 = tid & 7;
        const int grow = (c >> 3) * HH + u0 + (c & 7);
        const float* wr = Whh + (size_t)grow * HH;
        for (int q = 0; q < 32; q++) {
            const int k = e8 * 128 + q * 4;
            const float4 v = *(const float4*)(wr + k);
            const __nv_bfloat16 b0 = __float2bfloat16(v.x);
            const __nv_bfloat16 b1 = __float2bfloat16(v.y);
            const __nv_bfloat16 b2 = __float2bfloat16(v.z);
            const __nv_bfloat16 b3 = __float2bfloat16(v.w);
            BsH[c * BPITCH + k + 0] = b0;
            BsH[c * BPITCH + k + 1] = b1;
            BsH[c * BPITCH + k + 2] = b2;
            BsH[c * BPITCH + k + 3] = b3;
            BsL[c * BPITCH + k + 0] = __float2bfloat16(v.x - __bfloat162float(b0));
            BsL[c * BPITCH + k + 1] = __float2bfloat16(v.y - __bfloat162float(b1));
            BsL[c * BPITCH + k + 2] = __float2bfloat16(v.z - __bfloat162float(b2));
            BsL[c * BPITCH + k + 3] = __float2bfloat16(v.w - __bfloat162float(b3));
        }
    }
    if (tid < 32) Bh[tid] = bhh[(tid >> 3) * HH + u0 + (tid & 7)];
    Cs[tid] = 0.f;                          // 512 = 64*8 cell-state slots
    __syncthreads();

    // consumer tiles (warps 0-7)
    const int wm = warp & 3;               // M tile base (batch rows)
    const int wn = (warp >> 2) & 1;        // N tile base (local cols)
    const bool is_consumer = (warp < 8);

    // producer staging mapping (warps 8-15; 256 threads)
    const int ptid   = tid - 256;          // 0..255 for producers
    const int cp_row = (ptid & 255) >> 2;  // 0..63
    const int cp_q   = ptid & 3;           // 0..3

    // pointwise mapping: all 512 threads, 1 unit each
    const int pb = tid >> 3;               // batch 0..63
    const int pu = tid & 7;                // unit 0..7

    for (int t = 0; t < TT; t++) {
        wmma::fragment<wmma::accumulator, 16, 16, 16, float> fS, fHL, fLH;
        wmma::fill_fragment(fS, 0.0f);
        wmma::fill_fragment(fHL, 0.0f);
        wmma::fill_fragment(fLH, 0.0f);

        if (t > 0) {
            const __nv_bfloat16* hHp = g_hhi + (size_t)(t - 1) * BB * HH;
            const __nv_bfloat16* hLp = g_hlo + (size_t)(t - 1) * BB * HH;
            const size_t rbase = (size_t)cp_row * HH + cp_q * 16;

            // ---- producers stage chunk 0 into buf 0 ----
            if (!is_consumer) {
                const uint4 rh0 = *(const uint4*)(hHp + rbase);
                const uint4 rh1 = *(const uint4*)(hHp + rbase + 8);
                const uint4 rl0 = *(const uint4*)(hLp + rbase);
                const uint4 rl1 = *(const uint4*)(hLp + rbase + 8);
                const int so = cp_row * APITCH + cp_q * 16;
                *(uint4*)(AsH + so)     = rh0;
                *(uint4*)(AsH + so + 8) = rh1;
                *(uint4*)(AsL + so)     = rl0;
                *(uint4*)(AsL + so + 8) = rl1;
            }
            __syncthreads();

            for (int kt = 0; kt < 16; kt++) {          // 16 chunks of KCH=64
                const int buf = kt & 1;

                if (is_consumer) {
                    // ---- consumers: LDSM + MMA only ----
                    const __nv_bfloat16* aH = AsH + buf * 64 * APITCH + wm * 16 * APITCH;
                    const __nv_bfloat16* aL = AsL + buf * 64 * APITCH + wm * 16 * APITCH;
                    const __nv_bfloat16* bH = BsH + wn * 16 * BPITCH + kt * KCH;
                    const __nv_bfloat16* bL = BsL + wn * 16 * BPITCH + kt * KCH;
#pragma unroll
                    for (int ks = 0; ks < 4; ks++) {
                        wmma::fragment<wmma::matrix_a, 16, 16, 16, __nv_bfloat16, wmma::row_major> faH, faL;
                        wmma::fragment<wmma::matrix_b, 16, 16, 16, __nv_bfloat16, wmma::col_major> fbH, fbL;
                        wmma::load_matrix_sync(faH, aH + ks * 16, APITCH);
                        wmma::load_matrix_sync(faL, aL + ks * 16, APITCH);
                        wmma::load_matrix_sync(fbH, bH + ks * 16, BPITCH);
                        wmma::load_matrix_sync(fbL, bL + ks * 16, BPITCH);
                        wmma::mma_sync(fS,  faH, fbH, fS);
                        wmma::mma_sync(fHL, faH, fbL, fHL);
                        wmma::mma_sync(fLH, faL, fbH, fLH);
                    }
                } else if (kt < 15) {
                    // ---- producers: stage chunk kt+1 into buf^1 ----
                    const size_t ro = rbase + (size_t)(kt + 1) * KCH;
                    const uint4 rh0 = *(const uint4*)(hHp + ro);
                    const uint4 rh1 = *(const uint4*)(hHp + ro + 8);
                    const uint4 rl0 = *(const uint4*)(hLp + ro);
                    const uint4 rl1 = *(const uint4*)(hLp + ro + 8);
                    const int so = (buf ^ 1) * 64 * APITCH + cp_row * APITCH + cp_q * 16;
                    *(uint4*)(AsH + so)     = rh0;
                    *(uint4*)(AsH + so + 8) = rh1;
                    *(uint4*)(AsL + so)     = rl0;
                    *(uint4*)(AsL + so + 8) = rl1;
                }
                __syncthreads();
            }
        }

        // ---- consumers: sum chains, stash D tile to Gs [64 rows][pitch 40] ----
        if (is_consumer) {
#pragma unroll
            for (int e = 0; e < fS.num_elements; e++)
                fS.x[e] += fHL.x[e] + fLH.x[e];
            wmma::store_matrix_sync(Gs + wm * 16 * 40 + wn * 16, fS, 40, wmma::mem_row_major);
        }
        __syncthreads();

        // ---- pointwise: all 512 threads, one unit each ----
        {
            const size_t xbase = ((size_t)pb * TT + t) * G4 + u0 + pu;
            const float xi  = g_xg[xbase];
            const float xf  = g_xg[xbase + HH];
            const float xg2 = g_xg[xbase + 2 * HH];
            const float xo  = g_xg[xbase + 3 * HH];

            const float ri = Gs[pb * 40 + 0  + pu];
            const float rf = Gs[pb * 40 + 8  + pu];
            const float rg = Gs[pb * 40 + 16 + pu];
            const float ro = Gs[pb * 40 + 24 + pu];

            const float cp = Cs[pb * 8 + pu];

            const float i0 = 1.f / (1.f + expf(-(xi + ri + Bh[pu])));
            const float f0 = 1.f / (1.f + expf(-(xf + rf + Bh[8 + pu])));
            const float g0 = tanhf(xg2 + rg + Bh[16 + pu]);
            const float o0 = 1.f / (1.f + expf(-(xo + ro + Bh[24 + pu])));
            const float c0 = f0 * cp + i0 * g0;
            const float h0 = o0 * tanhf(c0);

            Cs[pb * 8 + pu] = c0;

            const __nv_bfloat16 hh = __float2bfloat16(h0);
            const __nv_bfloat16 hl = __float2bfloat16(h0 - __bfloat162float(hh));

            const size_t hidx = ((size_t)t * BB + pb) * HH + u0 + pu;
            g_hhi[hidx] = hh;
            g_hlo[hidx] = hl;
        }

        grid_sync_();
    }
}

// =====================================================================
// FC: out[b][t] = dot(h_t[b], W_fc) + b_fc   (h = hi + lo)
// =====================================================================
__global__ __launch_bounds__(128) void fc_kernel(const float* __restrict__ Wfc,
                                                 const float* __restrict__ bfc,
                                                 float* __restrict__ out)
{
    const int bt = blockIdx.x;
    const int t  = bt >> 6;
    const int b  = bt & 63;
    const size_t base = ((size_t)t * BB + b) * HH;
    const int tid = threadIdx.x;

    float s = 0.f;
#pragma unroll
    for (int q = 0; q < 8; q++) {
        const int j = tid + q * 128;
        const float h = __bfloat162float(g_hhi[base + j]) + __bfloat162float(g_hlo[base + j]);
        s += h * Wfc[j];
    }
#pragma unroll
    for (int off = 16; off; off >>= 1) s += __shfl_down_sync(0xffffffffu, s, off);

    __shared__ float red[4];
    if ((tid & 31) == 0) red[tid >> 5] = s;
    __syncthreads();
    if (tid == 0)
        out[(size_t)b * TT + t] = red[0] + red[1] + red[2] + red[3] + bfc[0];
}

// =====================================================================
extern "C" void kernel_launch(void* const* d_in, const int* in_sizes, int n_in,
                              void* d_out, int out_size)
{
    const float* x   = (const float*)d_in[0];
    const float* Wih = (const float*)d_in[1];
    const float* Whh = (const float*)d_in[2];
    const float* bih = (const float*)d_in[3];
    const float* bhh = (const float*)d_in[4];
    const float* Wfc = (const float*)d_in[5];
    const float* bfc = (const float*)d_in[6];
    float* out = (float*)d_out;

    cudaFuncSetAttribute(lstm_persistent,
                         cudaFuncAttributeMaxDynamicSharedMemorySize, (int)SMB_TOT);

    // 1) input projection (fp32 SIMT GEMM, known-good 3.0 ms)
    xg_gemm<<<dim3(G4 / 64, MM / 128), 256>>>(x, Wih, bih);

    // 2) full recurrence: persistent tensor-core kernel, warp-specialized staging
    lstm_persistent<<<NCTA, 512, SMB_TOT>>>(Whh, bhh);

    // 3) output projection
    fc_kernel<<<MM, 128>>>(Wfc, bfc, out);
}